// round 3
// baseline (speedup 1.0000x reference)
#include <cuda_runtime.h>
#include <mma.h>
#include <cstdint>
#include <cstddef>

using namespace nvcuda;

// ============================================================================
// Problem: hidden [B,2048] f32, labels [B,28] i64-or-i32, W [280,2048] f32,
// bias [280] f32.  logits = hidden @ W^T + bias;  loss = mean NLL / 28.
// Output (per reference): (loss, logits) -> detect layout from out_size.
// ============================================================================
static constexpr int KDIM = 2048;
static constexpr int NTOT = 280;    // 28 heads * 10 classes
static constexpr int NPAD = 288;    // 18 * 16 (wmma n-tiles)
static constexpr int BM   = 128;    // M rows per CTA
static constexpr int BK   = 32;     // K chunk
static constexpr int NCH  = KDIM / BK;   // 64
static constexpr int THREADS = 384; // 12 warps: 4 (m) x 3 (n)

static constexpr int LDA = 36;      // padded leading dims (floats)
static constexpr int LDB = 36;
static constexpr int LDC = 292;

// SMEM byte offsets
static constexpr int SM_BIAS = 0;                    // 288 f32
static constexpr int SM_A    = 1280;
static constexpr int A_SZ    = BM * LDA * 4;         // 18432
static constexpr int SM_B    = SM_A + 2 * A_SZ;      // 38144
static constexpr int B_SZ    = NPAD * LDB * 4;       // 41472
static constexpr int SM_TOTAL= SM_B + 2 * B_SZ;      // 121088
static constexpr int SM_C    = 1280;                 // reuse A/B area post-GEMM
// C half: 64 * 292 * 4 = 74752 <= 119808 available   ✓

// round-to-nearest tf32 conversion (load-bearing: HW truncation would bias
// logits by ~1e-3; RN keeps rel err ~2e-4).
// NOTE: cvt.rna.tf32.f32 destination is a .b32 register -> "=r" constraint.
__device__ __forceinline__ float to_tf32(float x) {
    uint32_t y;
    asm("cvt.rna.tf32.f32 %0, %1;" : "=r"(y) : "f"(x));
    return __uint_as_float(y);
}

// ============================================================================
// Device scratch / flags
// ============================================================================
__device__ float g_logits_scratch[32768 * NTOT];
__device__ float g_loss_scratch[1];
__device__ int   g_lab64;

// ============================================================================
// Label dtype detection: int64 labels (values 0..9) => odd 32-bit words zero.
// ============================================================================
__global__ void detect_labels_kernel(const int* __restrict__ lab) {
    if (threadIdx.x == 0) {
        int odd_or = 0;
        #pragma unroll 8
        for (int i = 0; i < 64; i++) odd_or |= lab[2 * i + 1];
        g_lab64 = (odd_or == 0) ? 1 : 0;
    }
}

// ============================================================================
// Fused GEMM (tf32 wmma) + bias + logits store + loss
// ============================================================================
__global__ void __launch_bounds__(THREADS, 1)
gemm_loss_kernel(const float* __restrict__ hidden,
                 const float* __restrict__ W,
                 const float* __restrict__ bias,
                 const int*   __restrict__ lab,
                 float* __restrict__ logits_arg,
                 float* __restrict__ loss_out,
                 int batch)
{
    extern __shared__ char smem[];
    float* sbias = reinterpret_cast<float*>(smem + SM_BIAS);
    float* logits = logits_arg ? logits_arg : g_logits_scratch;

    const int tid = threadIdx.x;
    const int wid = tid >> 5;
    const int wm  = wid & 3;    // 0..3  (32-row slice)
    const int wn  = wid >> 2;   // 0..2  (96-col slice)
    const int m0  = blockIdx.x * BM;

    for (int i = tid; i < NPAD; i += THREADS)
        sbias[i] = (i < NTOT) ? bias[i] : 0.f;

    wmma::fragment<wmma::accumulator, 16, 16, 8, float> c[2][6];
    #pragma unroll
    for (int i = 0; i < 2; i++)
        #pragma unroll
        for (int j = 0; j < 6; j++)
            wmma::fill_fragment(c[i][j], 0.f);

    // ---- cooperative chunk stage: A 128x32, B 288x32 (tf32-rounded) ----
    auto load_chunk = [&](int kc, int buf) {
        const int k0 = kc * BK;
        float* As = reinterpret_cast<float*>(smem + SM_A + buf * A_SZ);
        float* Bs = reinterpret_cast<float*>(smem + SM_B + buf * B_SZ);
        // A: 1024 float4
        #pragma unroll
        for (int i = 0; i < 3; i++) {
            int idx = tid + i * THREADS;
            if (idx < 1024) {
                int r = idx >> 3, v = idx & 7;
                float4 val = *reinterpret_cast<const float4*>(
                    hidden + (size_t)(m0 + r) * KDIM + k0 + v * 4);
                val.x = to_tf32(val.x); val.y = to_tf32(val.y);
                val.z = to_tf32(val.z); val.w = to_tf32(val.w);
                *reinterpret_cast<float4*>(As + r * LDA + v * 4) = val;
            }
        }
        // B: 2304 float4 (rows >= 280 zero)
        #pragma unroll
        for (int i = 0; i < 6; i++) {
            int idx = tid + i * THREADS;
            int r = idx >> 3, v = idx & 7;
            float4 val = make_float4(0.f, 0.f, 0.f, 0.f);
            if (r < NTOT) {
                val = *reinterpret_cast<const float4*>(
                    W + (size_t)r * KDIM + k0 + v * 4);
                val.x = to_tf32(val.x); val.y = to_tf32(val.y);
                val.z = to_tf32(val.z); val.w = to_tf32(val.w);
            }
            *reinterpret_cast<float4*>(Bs + r * LDB + v * 4) = val;
        }
    };

    load_chunk(0, 0);
    __syncthreads();

    for (int kc = 0; kc < NCH; kc++) {
        const int cur = kc & 1;
        const float* As = reinterpret_cast<const float*>(smem + SM_A + cur * A_SZ);
        const float* Bs = reinterpret_cast<const float*>(smem + SM_B + cur * B_SZ);

        #pragma unroll
        for (int ks = 0; ks < 4; ks++) {
            const int k0 = ks * 8;
            wmma::fragment<wmma::matrix_a, 16, 16, 8, wmma::precision::tf32,
                           wmma::row_major> a[2];
            wmma::fragment<wmma::matrix_b, 16, 16, 8, wmma::precision::tf32,
                           wmma::col_major> b[6];
            #pragma unroll
            for (int i = 0; i < 2; i++)
                wmma::load_matrix_sync(a[i], As + (wm * 32 + i * 16) * LDA + k0, LDA);
            #pragma unroll
            for (int j = 0; j < 6; j++)
                wmma::load_matrix_sync(b[j], Bs + (wn * 96 + j * 16) * LDB + k0, LDB);
            #pragma unroll
            for (int i = 0; i < 2; i++)
                #pragma unroll
                for (int j = 0; j < 6; j++)
                    wmma::mma_sync(c[i][j], a[i], b[j], c[i][j]);
        }

        if (kc + 1 < NCH) load_chunk(kc + 1, (kc + 1) & 1);
        __syncthreads();
    }

    // ---- epilogue: two 64-row halves through SMEM; bias + store + loss ----
    float* Cs = reinterpret_cast<float*>(smem + SM_C);
    const int lab64 = g_lab64;
    float loss_part = 0.f;

    #pragma unroll
    for (int half = 0; half < 2; half++) {
        if ((wm >> 1) == half) {
            const int rbase = (wm & 1) * 32;
            #pragma unroll
            for (int i = 0; i < 2; i++)
                #pragma unroll
                for (int j = 0; j < 6; j++)
                    wmma::store_matrix_sync(
                        Cs + (rbase + i * 16) * LDC + wn * 96 + j * 16,
                        c[i][j], LDC, wmma::mem_row_major);
        }
        __syncthreads();

        // logits write-out (with bias)
        for (int idx = tid; idx < 64 * NTOT; idx += THREADS) {
            int r = idx / NTOT, n = idx - r * NTOT;
            logits[(size_t)(m0 + half * 64 + r) * NTOT + n] =
                Cs[r * LDC + n] + sbias[n];
        }
        // loss: 64 rows x 28 heads
        for (int t = tid; t < 64 * 28; t += THREADS) {
            int r = t / 28, h = t - r * 28;
            const float* x  = Cs + r * LDC + h * 10;
            const float* bb = sbias + h * 10;
            float v[10], mx = -1e30f;
            #pragma unroll
            for (int i = 0; i < 10; i++) { v[i] = x[i] + bb[i]; mx = fmaxf(mx, v[i]); }
            float s = 0.f;
            #pragma unroll
            for (int i = 0; i < 10; i++) s += __expf(v[i] - mx);
            int row = m0 + half * 64 + r;
            int li  = row * 28 + h;
            int label = lab64 ? lab[2 * li] : lab[li];
            loss_part += mx + __logf(s) - v[label];
        }
        __syncthreads();
    }

    // block reduction of loss
    #pragma unroll
    for (int off = 16; off > 0; off >>= 1)
        loss_part += __shfl_xor_sync(0xFFFFFFFF, loss_part, off);
    __shared__ float warp_loss[12];
    if ((tid & 31) == 0) warp_loss[wid] = loss_part;
    __syncthreads();
    if (tid == 0) {
        float t = 0.f;
        #pragma unroll
        for (int i = 0; i < 12; i++) t += warp_loss[i];
        atomicAdd(loss_out, t * (1.0f / ((float)batch * 28.0f)));
    }
}

// ============================================================================
// kernel_launch
// ============================================================================
extern "C" void kernel_launch(void* const* d_in, const int* in_sizes, int n_in,
                              void* d_out, int out_size)
{
    const float* hidden = (const float*)d_in[0];
    const int*   labels = (const int*)d_in[1];
    const float* W      = (const float*)d_in[2];
    const float* bias   = (const float*)d_in[3];

    const int batch = in_sizes[0] / KDIM;                  // 32768
    const long long LOGN = (long long)batch * NTOT;

    float* out = (float*)d_out;
    float* loss_ptr = nullptr;
    float* logits_ptr = nullptr;
    if ((long long)out_size >= LOGN + 1) {        // (loss, logits) concat
        loss_ptr = out;
        logits_ptr = out + 1;
    } else if ((long long)out_size == LOGN) {     // logits only
        logits_ptr = out;
    } else {                                      // loss only
        loss_ptr = out;
    }
    if (!loss_ptr) {
        void* p = nullptr;
        cudaGetSymbolAddress(&p, g_loss_scratch);
        loss_ptr = (float*)p;
    }

    static bool attr_done = false;
    if (!attr_done) {
        cudaFuncSetAttribute(gemm_loss_kernel,
                             cudaFuncAttributeMaxDynamicSharedMemorySize, SM_TOTAL);
        attr_done = true;
    }

    detect_labels_kernel<<<1, 32>>>(labels);
    cudaMemsetAsync(loss_ptr, 0, sizeof(float));
    gemm_loss_kernel<<<batch / BM, THREADS, SM_TOTAL>>>(
        hidden, W, bias, labels, logits_ptr, loss_ptr, batch);
}

// round 4
// speedup vs baseline: 1.3149x; 1.3149x over previous
#include <cuda_runtime.h>
#include <mma.h>
#include <cstdint>
#include <cstddef>

using namespace nvcuda;

// ============================================================================
// Problem: hidden [B,2048] f32, labels [B,28] i64/i32, W [280,2048] f32,
// bias [280] f32.  logits = hidden @ W^T + bias;  loss = mean NLL / 28.
// ============================================================================
static constexpr int KDIM = 2048;
static constexpr int NTOT = 280;
static constexpr int NPAD = 288;       // 18 * 16
static constexpr int BM   = 128;
static constexpr int BK   = 32;
static constexpr int NCH  = KDIM / BK; // 64
static constexpr int THREADS = 384;    // 12 warps: 2 (m) x 6 (n)
static constexpr int STAGES = 3;

static constexpr int LDA = 36;
static constexpr int LDB = 36;
static constexpr int LDC = 292;

// SMEM layout (bytes)
static constexpr int SM_BIAS  = 0;                       // 288 f32
static constexpr int SM_STG   = 1280;
static constexpr int A_SZ     = BM * LDA * 4;            // 18432
static constexpr int B_SZ     = NPAD * LDB * 4;          // 41472
static constexpr int STAGE_SZ = A_SZ + B_SZ;             // 59904
static constexpr int SM_TOTAL = SM_STG + STAGES * STAGE_SZ;  // 180992
static constexpr int SM_C     = SM_STG;                  // epilogue reuses stages

// RN tf32 (used only in W prep; A uses HW truncation inside the MMA)
__device__ __forceinline__ float to_tf32(float x) {
    uint32_t y;
    asm("cvt.rna.tf32.f32 %0, %1;" : "=r"(y) : "f"(x));
    return __uint_as_float(y);
}

__device__ __forceinline__ uint32_t smem_u32(const void* p) {
    uint32_t a;
    asm("{ .reg .u64 t; cvta.to.shared.u64 t, %1; cvt.u32.u64 %0, t; }"
        : "=r"(a) : "l"(p));
    return a;
}

#define CP_ASYNC16(dst, src) \
    asm volatile("cp.async.cg.shared.global [%0], [%1], 16;" \
                 :: "r"(dst), "l"(src))
#define CP_COMMIT() asm volatile("cp.async.commit_group;" ::: "memory")
#define CP_WAIT(n)  asm volatile("cp.async.wait_group %0;" :: "n"(n) : "memory")

// ============================================================================
// Device scratch
// ============================================================================
__device__ float g_wpad[NPAD * KDIM];     // tf32-rounded, zero-padded W
__device__ float g_logits_scratch[32768 * NTOT];
__device__ float g_loss_scratch[1];
__device__ int   g_lab64;

// ============================================================================
// Prep: W -> g_wpad (RN tf32, rows >= 280 zero). Label dtype detect.
// ============================================================================
__global__ void prep_kernel(const float* __restrict__ W,
                            const int* __restrict__ lab) {
    int idx = blockIdx.x * blockDim.x + threadIdx.x;
    if (idx < NPAD * KDIM) {
        int r = idx >> 11;   // / 2048
        g_wpad[idx] = (r < NTOT) ? to_tf32(W[idx]) : 0.f;
    }
    if (idx == 0) {
        int odd_or = 0;
        #pragma unroll 8
        for (int i = 0; i < 64; i++) odd_or |= lab[2 * i + 1];
        g_lab64 = (odd_or == 0) ? 1 : 0;
    }
}

// ============================================================================
// Fused GEMM (tf32 wmma, cp.async 3-stage pipeline) + bias + logits + loss
// ============================================================================
__global__ void __launch_bounds__(THREADS, 1)
gemm_loss_kernel(const float* __restrict__ hidden,
                 const float* __restrict__ bias,
                 const int*   __restrict__ lab,
                 float* __restrict__ logits_arg,
                 float* __restrict__ loss_out,
                 int batch)
{
    extern __shared__ char smem[];
    float* sbias = reinterpret_cast<float*>(smem + SM_BIAS);
    float* logits = logits_arg ? logits_arg : g_logits_scratch;

    const uint32_t sbase = smem_u32(smem);
    const int tid = threadIdx.x;
    const int wid = tid >> 5;
    const int wm  = wid / 6;     // 0..1 -> 64-row slice
    const int wn  = wid % 6;     // 0..5 -> 48-col slice
    const int m0  = blockIdx.x * BM;

    for (int i = tid; i < NPAD; i += THREADS)
        sbias[i] = (i < NTOT) ? bias[i] : 0.f;

    wmma::fragment<wmma::accumulator, 16, 16, 8, float> c[4][3];
    #pragma unroll
    for (int i = 0; i < 4; i++)
        #pragma unroll
        for (int j = 0; j < 3; j++)
            wmma::fill_fragment(c[i][j], 0.f);

    // ---- cp.async stage issue: A 128x32 raw f32, B 288x32 pre-rounded ----
    auto issue_stage = [&](int kc, int buf) {
        const uint32_t a_dst = sbase + SM_STG + buf * STAGE_SZ;
        const uint32_t b_dst = a_dst + A_SZ;
        const int k0 = kc * BK;
        // A: 1024 x 16B
        #pragma unroll
        for (int i = 0; i < 3; i++) {
            int idx = tid + i * THREADS;
            if (idx < 1024) {
                int r = idx >> 3, v = idx & 7;
                const float* src = hidden + (size_t)(m0 + r) * KDIM + k0 + v * 4;
                CP_ASYNC16(a_dst + (uint32_t)(r * LDA + v * 4) * 4, src);
            }
        }
        // B: 2304 x 16B (6 per thread exact)
        #pragma unroll
        for (int i = 0; i < 6; i++) {
            int idx = tid + i * THREADS;
            int r = idx >> 3, v = idx & 7;
            const float* src = g_wpad + (size_t)r * KDIM + k0 + v * 4;
            CP_ASYNC16(b_dst + (uint32_t)(r * LDB + v * 4) * 4, src);
        }
    };

    issue_stage(0, 0); CP_COMMIT();
    issue_stage(1, 1); CP_COMMIT();

    for (int kc = 0; kc < NCH; kc++) {
        CP_WAIT(1);            // stage kc complete (kc+1 may be in flight)
        __syncthreads();

        const int buf = kc % STAGES;
        const float* As = reinterpret_cast<const float*>(
            smem + SM_STG + buf * STAGE_SZ);
        const float* Bs = As + A_SZ / 4;

        #pragma unroll
        for (int ks = 0; ks < 4; ks++) {
            const int k0 = ks * 8;
            wmma::fragment<wmma::matrix_a, 16, 16, 8, wmma::precision::tf32,
                           wmma::row_major> a[4];
            wmma::fragment<wmma::matrix_b, 16, 16, 8, wmma::precision::tf32,
                           wmma::col_major> b[3];
            #pragma unroll
            for (int i = 0; i < 4; i++)
                wmma::load_matrix_sync(a[i], As + (wm * 64 + i * 16) * LDA + k0, LDA);
            #pragma unroll
            for (int j = 0; j < 3; j++)
                wmma::load_matrix_sync(b[j], Bs + (wn * 48 + j * 16) * LDB + k0, LDB);
            #pragma unroll
            for (int i = 0; i < 4; i++)
                #pragma unroll
                for (int j = 0; j < 3; j++)
                    wmma::mma_sync(c[i][j], a[i], b[j], c[i][j]);
        }

        if (kc + 2 < NCH) issue_stage(kc + 2, (kc + 2) % STAGES);
        CP_COMMIT();           // keep group count uniform even when empty
    }
    __syncthreads();           // all warps done reading stage smem

    // ---- epilogue: two 64-row halves through SMEM; bias + store + loss ----
    float* Cs = reinterpret_cast<float*>(smem + SM_C);
    const int lab64 = g_lab64;
    float loss_part = 0.f;

    #pragma unroll
    for (int half = 0; half < 2; half++) {
        if (wm == half) {
            #pragma unroll
            for (int i = 0; i < 4; i++)
                #pragma unroll
                for (int j = 0; j < 3; j++)
                    wmma::store_matrix_sync(
                        Cs + (i * 16) * LDC + wn * 48 + j * 16,
                        c[i][j], LDC, wmma::mem_row_major);
        }
        __syncthreads();

        for (int idx = tid; idx < 64 * NTOT; idx += THREADS) {
            int r = idx / NTOT, n = idx - r * NTOT;
            logits[(size_t)(m0 + half * 64 + r) * NTOT + n] =
                Cs[r * LDC + n] + sbias[n];
        }
        for (int t = tid; t < 64 * 28; t += THREADS) {
            int r = t / 28, h = t - r * 28;
            const float* x  = Cs + r * LDC + h * 10;
            const float* bb = sbias + h * 10;
            float v[10], mx = -1e30f;
            #pragma unroll
            for (int i = 0; i < 10; i++) { v[i] = x[i] + bb[i]; mx = fmaxf(mx, v[i]); }
            float s = 0.f;
            #pragma unroll
            for (int i = 0; i < 10; i++) s += __expf(v[i] - mx);
            int row = m0 + half * 64 + r;
            int li  = row * 28 + h;
            int label = lab64 ? lab[2 * li] : lab[li];
            loss_part += mx + __logf(s) - v[label];
        }
        __syncthreads();
    }

    #pragma unroll
    for (int off = 16; off > 0; off >>= 1)
        loss_part += __shfl_xor_sync(0xFFFFFFFF, loss_part, off);
    __shared__ float warp_loss[12];
    if ((tid & 31) == 0) warp_loss[wid] = loss_part;
    __syncthreads();
    if (tid == 0) {
        float t = 0.f;
        #pragma unroll
        for (int i = 0; i < 12; i++) t += warp_loss[i];
        atomicAdd(loss_out, t * (1.0f / ((float)batch * 28.0f)));
    }
}

// ============================================================================
// kernel_launch
// ============================================================================
extern "C" void kernel_launch(void* const* d_in, const int* in_sizes, int n_in,
                              void* d_out, int out_size)
{
    const float* hidden = (const float*)d_in[0];
    const int*   labels = (const int*)d_in[1];
    const float* W      = (const float*)d_in[2];
    const float* bias   = (const float*)d_in[3];

    const int batch = in_sizes[0] / KDIM;                  // 32768
    const long long LOGN = (long long)batch * NTOT;

    float* out = (float*)d_out;
    float* loss_ptr = nullptr;
    float* logits_ptr = nullptr;
    if ((long long)out_size >= LOGN + 1) {
        loss_ptr = out;
        logits_ptr = out + 1;
    } else if ((long long)out_size == LOGN) {
        logits_ptr = out;
    } else {
        loss_ptr = out;
    }
    if (!loss_ptr) {
        void* p = nullptr;
        cudaGetSymbolAddress(&p, g_loss_scratch);
        loss_ptr = (float*)p;
    }

    static bool attr_done = false;
    if (!attr_done) {
        cudaFuncSetAttribute(gemm_loss_kernel,
                             cudaFuncAttributeMaxDynamicSharedMemorySize, SM_TOTAL);
        attr_done = true;
    }

    prep_kernel<<<(NPAD * KDIM + 255) / 256, 256>>>(W, labels);
    cudaMemsetAsync(loss_ptr, 0, sizeof(float));
    gemm_loss_kernel<<<batch / BM, THREADS, SM_TOTAL>>>(
        hidden, bias, labels, logits_ptr, loss_ptr, batch);
}